// round 16
// baseline (speedup 1.0000x reference)
#include <cuda_runtime.h>
#include <cuda_bf16.h>
#include <cstdint>
#include <cstddef>

// Problem constants
#define BB     8
#define MQ     512
#define NKV    2560
#define NH     16
#define HD     64
#define HID    1024
#define LW     2048
#define BH     128   // BB*NH
#define GRP    16    // head-batches per group (for P buffer)
#define NGRP   8     // BH / GRP

// ---------------- scratch (device globals; no allocation) ----------------
__device__ float g_q   [(size_t)BH * MQ  * HD];      //  16.8 MB  [bh, m, d], pre-scaled 1/8 (fp32 for pe)
__device__ float g_attn[(size_t)BB * MQ  * HID];     //  16.8 MB  [b*512+m, h*64+d] (gathered)
__device__ float g_P   [(size_t)GRP * MQ * LW];      //  67.1 MB  [bh_local*512+m, l]
// K/V stored pre-split bf16 hi/lo
__device__ __nv_bfloat16 g_kh[(size_t)BH * NKV * HD];  // 41.9 MB
__device__ __nv_bfloat16 g_kl[(size_t)BH * NKV * HD];  // 41.9 MB
__device__ __nv_bfloat16 g_vh[(size_t)BH * NKV * HD];  // 41.9 MB
__device__ __nv_bfloat16 g_vl[(size_t)BH * NKV * HD];  // 41.9 MB
// pre-split bf16 B-operand buffers
__device__ __nv_bfloat16 g_wh [(size_t)HID * HID];   //   2 MB
__device__ __nv_bfloat16 g_wl [(size_t)HID * HID];   //   2 MB
__device__ __nv_bfloat16 g_peh[(size_t)LW * HD];     // 256 KB (pe^T hi: [l, d])
__device__ __nv_bfloat16 g_pel[(size_t)LW * HD];     // 256 KB (pe^T lo)

// ======================= helpers =============================
__device__ __forceinline__ uint32_t smem_u32(const void* p) {
    uint32_t a;
    asm("{ .reg .u64 t; cvta.to.shared.u64 t, %1; cvt.u32.u64 %0, t; }" : "=r"(a) : "l"(p));
    return a;
}
__device__ __forceinline__ void ldsm_x4(uint32_t& r0, uint32_t& r1, uint32_t& r2, uint32_t& r3,
                                        uint32_t addr) {
    asm volatile("ldmatrix.sync.aligned.m8n8.x4.shared.b16 {%0,%1,%2,%3}, [%4];"
                 : "=r"(r0), "=r"(r1), "=r"(r2), "=r"(r3) : "r"(addr));
}
__device__ __forceinline__ void ldsm_x4_t(uint32_t& r0, uint32_t& r1, uint32_t& r2, uint32_t& r3,
                                          uint32_t addr) {
    asm volatile("ldmatrix.sync.aligned.m8n8.x4.trans.shared.b16 {%0,%1,%2,%3}, [%4];"
                 : "=r"(r0), "=r"(r1), "=r"(r2), "=r"(r3) : "r"(addr));
}
__device__ __forceinline__ void mma16816(float& d0, float& d1, float& d2, float& d3,
                                         uint32_t a0, uint32_t a1, uint32_t a2, uint32_t a3,
                                         uint32_t b0, uint32_t b1) {
    asm volatile("mma.sync.aligned.m16n8k16.row.col.f32.bf16.bf16.f32 "
                 "{%0,%1,%2,%3}, {%4,%5,%6,%7}, {%8,%9}, {%0,%1,%2,%3};"
                 : "+f"(d0), "+f"(d1), "+f"(d2), "+f"(d3)
                 : "r"(a0), "r"(a1), "r"(a2), "r"(a3), "r"(b0), "r"(b1));
}
__device__ __forceinline__ void split2(float x, float y, uint32_t& hp, uint32_t& lp) {
    __nv_bfloat16 h0 = __float2bfloat16_rn(x), h1 = __float2bfloat16_rn(y);
    __nv_bfloat16 l0 = __float2bfloat16_rn(x - __bfloat162float(h0));
    __nv_bfloat16 l1 = __float2bfloat16_rn(y - __bfloat162float(h1));
    __nv_bfloat162 th(h0, h1), tl(l0, l1);
    hp = *(uint32_t*)&th; lp = *(uint32_t*)&tl;
}

// =========================================================================
// split_w: fp32 [n] -> bf16 hi/lo (elementwise, float4)
// =========================================================================
__global__ __launch_bounds__(256)
void split_w(const float* __restrict__ in, __nv_bfloat16* __restrict__ hi,
             __nv_bfloat16* __restrict__ lo, int n4)
{
    int i = blockIdx.x * 256 + threadIdx.x;
    if (i >= n4) return;
    float4 x = ((const float4*)in)[i];
    uint32_t h0, l0, h1, l1;
    split2(x.x, x.y, h0, l0);
    split2(x.z, x.w, h1, l1);
    ((uint2*)hi)[i] = make_uint2(h0, h1);
    ((uint2*)lo)[i] = make_uint2(l0, l1);
}

// =========================================================================
// split_peT: pe[d, l] (64 x 2048) -> peT hi/lo [l, d] (2048 x 64)
// =========================================================================
__global__ __launch_bounds__(256)
void split_peT(const float* __restrict__ pe, __nv_bfloat16* __restrict__ hi,
               __nv_bfloat16* __restrict__ lo)
{
    int idx = blockIdx.x * 256 + threadIdx.x;
    if (idx >= LW * HD) return;
    int d = idx & 63;
    int l = idx >> 6;
    float x = pe[(size_t)d * LW + l];
    __nv_bfloat16 h = __float2bfloat16_rn(x);
    __nv_bfloat16 ll = __float2bfloat16_rn(x - __bfloat162float(h));
    hi[idx] = h;
    lo[idx] = ll;
}

// =========================================================================
// mma.sync split-bf16 GEMM:  C[rows, N] = A[rows, K] @ B[N, K]^T
// mode 0: fp32 row-major (ldc). mode 1: fp32 head-scatter.
// mode 2: bf16 hi/lo head-scatter (outh/outl).
// =========================================================================
#define SA_H    0
#define SA_L    (64  * 80)
#define SB_H    (2 * 64 * 80)
#define SB_L    (SB_H + 128 * 80)
#define SMEMSZ  (SB_L + 128 * 80)

__global__ __launch_bounds__(256, 2)
void tc_gemm_mma(const float* __restrict__ A,
                 const __nv_bfloat16* __restrict__ Bh, const __nv_bfloat16* __restrict__ Bl,
                 float* __restrict__ out,
                 __nv_bfloat16* __restrict__ outh, __nv_bfloat16* __restrict__ outl,
                 int lda, int K, int ldc, int seq, float scale, int mode)
{
    __shared__ __align__(16) uint8_t smem[SMEMSZ];
    const uint32_t sb = smem_u32(smem);

    const int tid  = threadIdx.x;
    const int lane = tid & 31;
    const int wid  = tid >> 5;
    const int wm   = (wid & 3) << 4;
    const int wn   = (wid >> 2) << 6;
    const int row0 = blockIdx.y << 6;
    const int col0 = blockIdx.x << 7;

    float acc[8][4];
#pragma unroll
    for (int j = 0; j < 8; j++)
#pragma unroll
        for (int q = 0; q < 4; q++) acc[j][q] = 0.f;

    const int lrow = lane & 15;
    const int lcol = (lane >> 4) << 4;

    for (int ks = 0; ks < K; ks += 32) {
        __syncthreads();
#pragma unroll
        for (int u = 0; u < 2; u++) {
            int v = (u << 8) + tid;
            int r = v >> 3;
            int c4 = (v & 7) << 2;
            float4 x = *(const float4*)(A + (size_t)(row0 + r) * lda + ks + c4);
            uint32_t hp0, lp0, hp1, lp1;
            split2(x.x, x.y, hp0, lp0);
            split2(x.z, x.w, hp1, lp1);
            uint32_t off = r * 80 + (c4 << 1);
            *(uint2*)(smem + SA_H + off) = make_uint2(hp0, hp1);
            *(uint2*)(smem + SA_L + off) = make_uint2(lp0, lp1);
        }
#pragma unroll
        for (int u = 0; u < 2; u++) {
            int v = (u << 8) + tid;
            int r = v >> 2;
            int cb = (v & 3) << 3;
            uint32_t off = r * 80 + (cb << 1);
            *(uint4*)(smem + SB_H + off) = *(const uint4*)(Bh + (size_t)(col0 + r) * K + ks + cb);
            *(uint4*)(smem + SB_L + off) = *(const uint4*)(Bl + (size_t)(col0 + r) * K + ks + cb);
        }
        __syncthreads();

#pragma unroll
        for (int kk = 0; kk < 2; kk++) {
            const uint32_t kb = (kk << 5);
            uint32_t ah0, ah1, ah2, ah3, al0, al1, al2, al3;
            {
                uint32_t ar = sb + SA_H + (wm + lrow) * 80 + kb + lcol;
                ldsm_x4(ah0, ah1, ah2, ah3, ar);
                ldsm_x4(al0, al1, al2, al3, ar + (SA_L - SA_H));
            }
            uint32_t bh[8][2];
#pragma unroll
            for (int p = 0; p < 4; p++) {
                uint32_t br = sb + SB_H + (wn + (p << 4) + lrow) * 80 + kb + lcol;
                uint32_t r0, r1, r2, r3;
                ldsm_x4(r0, r1, r2, r3, br);
                bh[2*p][0] = r0; bh[2*p][1] = r2;
                bh[2*p+1][0] = r1; bh[2*p+1][1] = r3;
            }
#pragma unroll
            for (int j = 0; j < 8; j++) {
                mma16816(acc[j][0], acc[j][1], acc[j][2], acc[j][3],
                         ah0, ah1, ah2, ah3, bh[j][0], bh[j][1]);
                mma16816(acc[j][0], acc[j][1], acc[j][2], acc[j][3],
                         al0, al1, al2, al3, bh[j][0], bh[j][1]);
            }
#pragma unroll
            for (int p = 0; p < 4; p++) {
                uint32_t br = sb + SB_L + (wn + (p << 4) + lrow) * 80 + kb + lcol;
                uint32_t r0, r1, r2, r3;
                ldsm_x4(r0, r1, r2, r3, br);
                bh[2*p][0] = r0; bh[2*p][1] = r2;
                bh[2*p+1][0] = r1; bh[2*p+1][1] = r3;
            }
#pragma unroll
            for (int j = 0; j < 8; j++) {
                mma16816(acc[j][0], acc[j][1], acc[j][2], acc[j][3],
                         ah0, ah1, ah2, ah3, bh[j][0], bh[j][1]);
            }
        }
    }

    const int r_lo = row0 + wm + (lane >> 2);
    const int c_base = col0 + wn + ((lane & 3) << 1);
#pragma unroll
    for (int j = 0; j < 8; j++) {
        int col = c_base + (j << 3);
#pragma unroll
        for (int half = 0; half < 2; half++) {
            int r = r_lo + (half << 3);
            float v0 = acc[j][half * 2 + 0] * scale;
            float v1 = acc[j][half * 2 + 1] * scale;
            if (mode == 1) {
                int b = r / seq;
                int s = r - b * seq;
                int h = col >> 6;
                int d = col & 63;
                float* op = out + (((size_t)(b * NH + h)) * seq + s) * 64 + d;
                op[0] = v0; op[1] = v1;
            } else if (mode == 2) {
                int b = r / seq;
                int s = r - b * seq;
                int h = col >> 6;
                int d = col & 63;
                size_t off = (((size_t)(b * NH + h)) * seq + s) * 64 + d;
                uint32_t hp, lp;
                split2(v0, v1, hp, lp);
                *(uint32_t*)(outh + off) = hp;
                *(uint32_t*)(outl + off) = lp;
            } else {
                float* op = out + (size_t)r * ldc + col;
                op[0] = v0; op[1] = v1;
            }
        }
    }
}

// =========================================================================
// attn_mma: flash attention on mma.sync with precomputed pos-bias P.
// Block = (64-query m-tile, bh in group). 256 thr, warps 4(m) x 2(n).
// =========================================================================
#define AQ_H   0
#define AQ_L   9216
#define AK_H   18432
#define AK_L   27648
#define AVS_H  36864
#define AVS_L  46080
#define AP_H   55296
#define AP_L   64512
#define ARED   73728               // float [2][64] row-max partials
#define ARED2  74240               // float [2][64] row-sum partials
#define ASMEM  74752

__global__ __launch_bounds__(256)
void attn_mma(const float* __restrict__ gq,
              const __nv_bfloat16* __restrict__ gkh, const __nv_bfloat16* __restrict__ gkl,
              const __nv_bfloat16* __restrict__ gvh, const __nv_bfloat16* __restrict__ gvl,
              const float* __restrict__ gP, float* __restrict__ gout, int bh0)
{
    extern __shared__ __align__(16) char smc[];
    const uint32_t sb = smem_u32(smc);
    const int tid  = threadIdx.x;
    const int lane = tid & 31;
    const int wid  = tid >> 5;
    const int wm   = (wid & 3) << 4;
    const int wns  = (wid >> 2) << 5;
    const int nh   = wid >> 2;
    const int lrow = lane & 15;
    const int lcol = (lane >> 4) << 4;
    const int bhl  = blockIdx.y;
    const int bh   = bh0 + bhl;
    const int m0   = blockIdx.x << 6;

    // ---- load + split Q tile (64x64 fp32 -> bf16 hi/lo), once ----
    {
        const float* qp = gq + (((size_t)bh * MQ + m0) << 6);
#pragma unroll
        for (int u = 0; u < 4; u++) {
            int v = (u << 8) + tid;
            int r = v >> 4;
            int c4 = (v & 15) << 2;
            float4 x = *(const float4*)(qp + (r << 6) + c4);
            uint32_t hp0, lp0, hp1, lp1;
            split2(x.x, x.y, hp0, lp0);
            split2(x.z, x.w, hp1, lp1);
            uint32_t off = r * 144 + (c4 << 1);
            *(uint2*)(smc + AQ_H + off) = make_uint2(hp0, hp1);
            *(uint2*)(smc + AQ_L + off) = make_uint2(lp0, lp1);
        }
    }

    float o4[4][4];
#pragma unroll
    for (int t = 0; t < 4; t++)
#pragma unroll
        for (int q = 0; q < 4; q++) o4[t][q] = 0.f;
    float mr1 = -1e30f, mr2 = -1e30f, lr1 = 0.f, lr2 = 0.f;

    const int r1 = wm + (lane >> 2);
    const int r2 = r1 + 8;
    const size_t Pbase = (((size_t)bhl) * MQ + m0) << 11;
    const float* P1 = gP + Pbase + ((size_t)r1 << 11);
    const float* P2 = gP + Pbase + ((size_t)r2 << 11);
    float* redm = (float*)(smc + ARED);
    float* reds = (float*)(smc + ARED2);

    for (int c = 0; c <= 32; c++) {
        const int c64 = c << 6;
        const int j0  = m0 + c64;
        __syncthreads();
        // ---- stage K/V (bf16 hi/lo, pure copies) ----
        {
            const size_t kvb = ((size_t)bh * NKV + j0) << 6;
#pragma unroll
            for (int u = 0; u < 8; u++) {
                int v = (u << 8) + tid;
                int rem = v & 511;
                int row = rem >> 3;
                int sg = (rem & 7) << 3;
                const __nv_bfloat16* sp = (u < 2) ? gkh : (u < 4) ? gkl : (u < 6) ? gvh : gvl;
                const uint32_t db = (u < 2) ? AK_H : (u < 4) ? AK_L : (u < 6) ? AVS_H : AVS_L;
                *(uint4*)(smc + db + row * 144 + (sg << 1)) =
                    *(const uint4*)(sp + kvb + ((size_t)row << 6) + sg);
            }
        }
        __syncthreads();

        // ---- QK: S[64x64], warp tile 16 x 32 (4 n-tiles), 3 passes ----
        float s4[4][4];
#pragma unroll
        for (int t = 0; t < 4; t++)
#pragma unroll
            for (int q = 0; q < 4; q++) s4[t][q] = 0.f;
#pragma unroll
        for (int kk = 0; kk < 4; kk++) {
            const uint32_t kb = kk << 5;
            uint32_t qh[4], ql[4];
            {
                uint32_t ar = sb + AQ_H + (wm + lrow) * 144 + kb + lcol;
                ldsm_x4(qh[0], qh[1], qh[2], qh[3], ar);
                ldsm_x4(ql[0], ql[1], ql[2], ql[3], ar + (AQ_L - AQ_H));
            }
            uint32_t bkh[4][2], bkl[4][2];
#pragma unroll
            for (int p = 0; p < 2; p++) {
                uint32_t br = sb + AK_H + (wns + (p << 4) + lrow) * 144 + kb + lcol;
                uint32_t t0, t1, t2, t3;
                ldsm_x4(t0, t1, t2, t3, br);
                bkh[2*p][0] = t0; bkh[2*p][1] = t2;
                bkh[2*p+1][0] = t1; bkh[2*p+1][1] = t3;
                ldsm_x4(t0, t1, t2, t3, br + (AK_L - AK_H));
                bkl[2*p][0] = t0; bkl[2*p][1] = t2;
                bkl[2*p+1][0] = t1; bkl[2*p+1][1] = t3;
            }
#pragma unroll
            for (int t = 0; t < 4; t++) {
                mma16816(s4[t][0], s4[t][1], s4[t][2], s4[t][3],
                         qh[0], qh[1], qh[2], qh[3], bkh[t][0], bkh[t][1]);
                mma16816(s4[t][0], s4[t][1], s4[t][2], s4[t][3],
                         ql[0], ql[1], ql[2], ql[3], bkh[t][0], bkh[t][1]);
                mma16816(s4[t][0], s4[t][1], s4[t][2], s4[t][3],
                         qh[0], qh[1], qh[2], qh[3], bkl[t][0], bkl[t][1]);
            }
        }

        // ---- pos-bias + band mask (l = c64 + jj - i, valid iff 0<=l<2048) ----
#pragma unroll
        for (int t = 0; t < 4; t++) {
            const int ct = wns + (t << 3) + ((lane & 3) << 1);
            int l1 = c64 + ct - r1;
            int l2 = c64 + ct - r2;
            if ((unsigned)l1 < (unsigned)LW) s4[t][0] += __ldg(P1 + l1); else s4[t][0] = -1e30f;
            if ((unsigned)(l1+1) < (unsigned)LW) s4[t][1] += __ldg(P1 + l1 + 1); else s4[t][1] = -1e30f;
            if ((unsigned)l2 < (unsigned)LW) s4[t][2] += __ldg(P2 + l2); else s4[t][2] = -1e30f;
            if ((unsigned)(l2+1) < (unsigned)LW) s4[t][3] += __ldg(P2 + l2 + 1); else s4[t][3] = -1e30f;
        }

        // ---- online softmax: quad-shfl partials + cross-warp smem combine ----
        float pm1 = -1e30f, pm2 = -1e30f;
#pragma unroll
        for (int t = 0; t < 4; t++) {
            pm1 = fmaxf(pm1, fmaxf(s4[t][0], s4[t][1]));
            pm2 = fmaxf(pm2, fmaxf(s4[t][2], s4[t][3]));
        }
        pm1 = fmaxf(pm1, __shfl_xor_sync(0xffffffffu, pm1, 1));
        pm1 = fmaxf(pm1, __shfl_xor_sync(0xffffffffu, pm1, 2));
        pm2 = fmaxf(pm2, __shfl_xor_sync(0xffffffffu, pm2, 1));
        pm2 = fmaxf(pm2, __shfl_xor_sync(0xffffffffu, pm2, 2));
        if ((lane & 3) == 0) { redm[nh * 64 + r1] = pm1; redm[nh * 64 + r2] = pm2; }
        __syncthreads();
        const float cm1 = fmaxf(redm[r1], redm[64 + r1]);
        const float cm2 = fmaxf(redm[r2], redm[64 + r2]);
        const float mn1 = fmaxf(mr1, cm1), mn2 = fmaxf(mr2, cm2);
        const float corr1 = __expf(mr1 - mn1), corr2 = __expf(mr2 - mn2);
        mr1 = mn1; mr2 = mn2;
        float ps1 = 0.f, ps2 = 0.f;
#pragma unroll
        for (int t = 0; t < 4; t++) {
            const int ct = wns + (t << 3) + ((lane & 3) << 1);
            float e0 = __expf(s4[t][0] - mn1);
            float e1 = __expf(s4[t][1] - mn1);
            float e2 = __expf(s4[t][2] - mn2);
            float e3 = __expf(s4[t][3] - mn2);
            ps1 += e0 + e1;
            ps2 += e2 + e3;
            uint32_t hp, lp;
            split2(e0, e1, hp, lp);
            *(uint32_t*)(smc + AP_H + r1 * 144 + (ct << 1)) = hp;
            *(uint32_t*)(smc + AP_L + r1 * 144 + (ct << 1)) = lp;
            split2(e2, e3, hp, lp);
            *(uint32_t*)(smc + AP_H + r2 * 144 + (ct << 1)) = hp;
            *(uint32_t*)(smc + AP_L + r2 * 144 + (ct << 1)) = lp;
        }
        ps1 += __shfl_xor_sync(0xffffffffu, ps1, 1);
        ps1 += __shfl_xor_sync(0xffffffffu, ps1, 2);
        ps2 += __shfl_xor_sync(0xffffffffu, ps2, 1);
        ps2 += __shfl_xor_sync(0xffffffffu, ps2, 2);
        if ((lane & 3) == 0) { reds[nh * 64 + r1] = ps1; reds[nh * 64 + r2] = ps2; }
        __syncthreads();
        lr1 = lr1 * corr1 + reds[r1] + reds[64 + r1];
        lr2 = lr2 * corr2 + reds[r2] + reds[64 + r2];
#pragma unroll
        for (int t = 0; t < 4; t++) {
            o4[t][0] *= corr1; o4[t][1] *= corr1;
            o4[t][2] *= corr2; o4[t][3] *= corr2;
        }

        // ---- AV: O += P @ V, V^T via ldsm.trans, 3 passes ----
#pragma unroll
        for (int kk = 0; kk < 4; kk++) {
            const uint32_t kb = kk << 5;
            uint32_t ph[4], pl[4];
            {
                uint32_t ar = sb + AP_H + (wm + lrow) * 144 + kb + lcol;
                ldsm_x4(ph[0], ph[1], ph[2], ph[3], ar);
                ldsm_x4(pl[0], pl[1], pl[2], pl[3], ar + (AP_L - AP_H));
            }
            uint32_t bvh[4][2], bvl[4][2];
#pragma unroll
            for (int p = 0; p < 2; p++) {
                uint32_t br = sb + AVS_H + ((kk << 4) + lrow) * 144 + ((wns + (p << 4)) << 1) + lcol;
                uint32_t t0, t1, t2, t3;
                ldsm_x4_t(t0, t1, t2, t3, br);
                bvh[2*p][0] = t0; bvh[2*p][1] = t1;
                bvh[2*p+1][0] = t2; bvh[2*p+1][1] = t3;
                ldsm_x4_t(t0, t1, t2, t3, br + (AVS_L - AVS_H));
                bvl[2*p][0] = t0; bvl[2*p][1] = t1;
                bvl[2*p+1][0] = t2; bvl[2*p+1][1] = t3;
            }
#pragma unroll
            for (int t = 0; t < 4; t++) {
                mma16816(o4[t][0], o4[t][1], o4[t][2], o4[t][3],
                         ph[0], ph[1], ph[2], ph[3], bvh[t][0], bvh[t][1]);
                mma16816(o4[t][0], o4[t][1], o4[t][2], o4[t][3],
                         pl[0], pl[1], pl[2], pl[3], bvh[t][0], bvh[t][1]);
                mma16816(o4[t][0], o4[t][1], o4[t][2], o4[t][3],
                         ph[0], ph[1], ph[2], ph[3], bvl[t][0], bvl[t][1]);
            }
        }
    }

    // ---- epilogue: normalize, write gathered fp32 ----
    const float inv1 = 1.f / lr1;
    const float inv2 = 1.f / lr2;
    const int bb = bh >> 4;
    const int hh = bh & 15;
    const size_t grow1 = (size_t)bb * MQ + m0 + r1;
    const size_t grow2 = (size_t)bb * MQ + m0 + r2;
#pragma unroll
    for (int t = 0; t < 4; t++) {
        const int dt = wns + (t << 3) + ((lane & 3) << 1);
        float2 a = make_float2(o4[t][0] * inv1, o4[t][1] * inv1);
        float2 b = make_float2(o4[t][2] * inv2, o4[t][3] * inv2);
        *(float2*)(gout + grow1 * HID + (hh << 6) + dt) = a;
        *(float2*)(gout + grow2 * HID + (hh << 6) + dt) = b;
    }
}

// =========================================================================
// host launcher
// =========================================================================
extern "C" void kernel_launch(void* const* d_in, const int* in_sizes, int n_in,
                              void* d_out, int out_size)
{
    const float* query  = (const float*)d_in[0];
    const float* key    = (const float*)d_in[1];
    const float* value  = (const float*)d_in[2];
    const float* key_pe = (const float*)d_in[3];
    const float* Wq     = (const float*)d_in[4];
    const float* Wk     = (const float*)d_in[5];
    const float* Wv     = (const float*)d_in[6];
    const float* Wo     = (const float*)d_in[7];
    float* out = (float*)d_out;

    float *pq, *pa, *pP;
    __nv_bfloat16 *kh, *kl, *vh, *vl, *wh, *wl, *peh, *pel;
    cudaGetSymbolAddress((void**)&pq, g_q);
    cudaGetSymbolAddress((void**)&pa, g_attn);
    cudaGetSymbolAddress((void**)&pP, g_P);
    cudaGetSymbolAddress((void**)&kh, g_kh);
    cudaGetSymbolAddress((void**)&kl, g_kl);
    cudaGetSymbolAddress((void**)&vh, g_vh);
    cudaGetSymbolAddress((void**)&vl, g_vl);
    cudaGetSymbolAddress((void**)&wh, g_wh);
    cudaGetSymbolAddress((void**)&wl, g_wl);
    cudaGetSymbolAddress((void**)&peh, g_peh);
    cudaGetSymbolAddress((void**)&pel, g_pel);

    const int nW4 = HID * HID / 4;
    const int wblk = (nW4 + 255) / 256;

    // ---- projections (Q fp32 head-scatter; K/V split-bf16 head-scatter) ----
    split_w<<<wblk, 256>>>(Wq, wh, wl, nW4);
    tc_gemm_mma<<<dim3(8, BB * MQ  / 64), 256>>>(query, wh, wl, pq, nullptr, nullptr,
                                                 HID, HID, HID, MQ,  0.125f, 1);
    split_w<<<wblk, 256>>>(Wk, wh, wl, nW4);
    tc_gemm_mma<<<dim3(8, BB * NKV / 64), 256>>>(key,   wh, wl, nullptr, kh, kl,
                                                 HID, HID, HID, NKV, 1.0f,   2);
    split_w<<<wblk, 256>>>(Wv, wh, wl, nW4);
    tc_gemm_mma<<<dim3(8, BB * NKV / 64), 256>>>(value, wh, wl, nullptr, vh, vl,
                                                 HID, HID, HID, NKV, 1.0f,   2);

    // ---- pe^T pre-split, then grouped pos-bias GEMM + mma attention ----
    split_peT<<<(LW * HD + 255) / 256, 256>>>(key_pe, peh, pel);
    (void)cudaFuncSetAttribute(attn_mma, cudaFuncAttributeMaxDynamicSharedMemorySize, ASMEM);
    for (int g = 0; g < NGRP; g++) {
        const float* qg = pq + (size_t)g * GRP * MQ * HD;
        tc_gemm_mma<<<dim3(LW / 128, GRP * MQ / 64), 256>>>(qg, peh, pel, pP, nullptr, nullptr,
                                                            HD, HD, LW, MQ, 1.0f, 0);
        attn_mma<<<dim3(8, GRP), 256, ASMEM>>>(pq, kh, kl, vh, vl, pP, pa, g * GRP);
    }

    // ---- output projection ----
    split_w<<<wblk, 256>>>(Wo, wh, wl, nW4);
    tc_gemm_mma<<<dim3(8, BB * MQ / 64), 256>>>(pa, wh, wl, out, nullptr, nullptr,
                                                HID, HID, HID, MQ, 1.0f, 0);
}